// round 3
// baseline (speedup 1.0000x reference)
#include <cuda_runtime.h>
#include <math.h>

#define BATCH 256
#define SEQ   512
#define DIN   64
#define HID   256

__device__ float g_bufA[(size_t)BATCH * SEQ * HID];   // 128 MiB
__device__ float g_bufB[(size_t)BATCH * SEQ * HID];   // 128 MiB
__device__ float g_hfin[(size_t)BATCH * HID];

// ---------------------------------------------------------------------------
// helpers
// ---------------------------------------------------------------------------
__device__ __forceinline__ unsigned long long ffma2(unsigned long long a,
                                                    unsigned long long b,
                                                    unsigned long long c) {
    unsigned long long d;
    asm("fma.rn.f32x2 %0, %1, %2, %3;" : "=l"(d) : "l"(a), "l"(b), "l"(c));
    return d;
}
__device__ __forceinline__ float2 u2f(unsigned long long v) {
    float2 r;
    asm("mov.b64 {%0, %1}, %2;" : "=f"(r.x), "=f"(r.y) : "l"(v));
    return r;
}
__device__ __forceinline__ unsigned long long pack2(float a, float b) {
    unsigned long long r;
    asm("mov.b64 %0, {%1, %2};" : "=l"(r) : "f"(a), "f"(b));
    return r;
}
__device__ __forceinline__ float tanh_fast(float x) {
    float r;
    asm("tanh.approx.f32 %0, %1;" : "=f"(r) : "f"(x));
    return r;
}

// ---------------------------------------------------------------------------
// Recurrence v3: 128 blocks x 1024 threads, 2 batch rows per block.
// Thread t: o = t>>2 (output 0..255), kq = t&3 (64-float k-strip).
// 48 weight floats in registers (24 u64), 16 from smem (4 ulonglong2).
// h double-buffered in smem: 4 chunks of 64 floats, chunk c at offset c*68
// (skew 4) -> the 4 distinct per-warp LDS.128 addresses are bank-disjoint.
// Reduction over kq via 2 shfl.xor rounds (kq = lane bits 0..1).
// ---------------------------------------------------------------------------
#define W_SMEM_BYTES  (4 * 1024 * 16)     // 64 KB: ulonglong2[4][1024]
#define H_ROW_F       272                 // 4 chunks * 68 floats
#define H_BUF_F       (2 * H_ROW_F)       // 544 floats per buffer (2 rows)
#define RNN3_SMEM     (W_SMEM_BYTES + 2 * H_BUF_F * 4)

__global__ __launch_bounds__(1024, 1) void rnn_recur3(
    const float* __restrict__ xp,      // [BATCH, SEQ, HID] (bias pre-added)
    const float* __restrict__ Whh,     // [HID, HID]
    float* __restrict__ out_seq,       // [BATCH, SEQ, HID] or null
    float* __restrict__ out_final)     // [BATCH, HID] or null
{
    extern __shared__ char smem_raw[];
    ulonglong2* wsm  = reinterpret_cast<ulonglong2*>(smem_raw);   // [4][1024]
    float*      hbuf = reinterpret_cast<float*>(smem_raw + W_SMEM_BYTES);

    const int t  = threadIdx.x;
    const int o  = t >> 2;      // 0..255
    const int kq = t & 3;       // 0..3
    const int k0 = kq * 64;

    // weights: Whh[o, k0 .. k0+47] -> regs, [k0+48 .. k0+63] -> smem
    unsigned long long w[24];
    {
        const ulonglong2* wr =
            reinterpret_cast<const ulonglong2*>(Whh + o * HID + k0);
#pragma unroll
        for (int j = 0; j < 12; j++) {
            ulonglong2 v = wr[j];
            w[2 * j]     = v.x;
            w[2 * j + 1] = v.y;
        }
#pragma unroll
        for (int j = 0; j < 4; j++) wsm[j * 1024 + t] = wr[12 + j];
    }

    for (int i = t; i < 2 * H_BUF_F; i += 1024) hbuf[i] = 0.0f;
    __syncthreads();

    // writers: kq==0 -> row 0, kq==1 -> row 1 (each holds full d0,d1 after
    // the shuffle reduction; kq picks which row this lane commits)
    const bool writer = (kq < 2);
    const int  grow   = blockIdx.x * 2 + kq;          // valid when writer
    const float* myxp = writer ? xp + ((size_t)grow * SEQ) * HID + o
                               : xp;
    float* myout = (out_seq && writer)
                       ? out_seq + ((size_t)grow * SEQ) * HID + o
                       : (float*)0;
    const int wslot = kq * H_ROW_F + (o >> 6) * 68 + (o & 63);

    int   buf   = 0;
    float hlast = 0.0f;

    for (int s = 0; s < SEQ; s++) {
        float xv = 0.0f;
        if (writer) xv = __ldg(myxp + (size_t)s * HID);

        const float* hb = hbuf + buf * H_BUF_F;
        const ulonglong2* h0 =
            reinterpret_cast<const ulonglong2*>(hb + kq * 68);
        const ulonglong2* h1 =
            reinterpret_cast<const ulonglong2*>(hb + H_ROW_F + kq * 68);

        unsigned long long a0 = 0ull, a1 = 0ull;
#pragma unroll
        for (int j = 0; j < 12; j++) {
            ulonglong2 hv0 = h0[j];
            ulonglong2 hv1 = h1[j];
            a0 = ffma2(w[2 * j],     hv0.x, a0);
            a0 = ffma2(w[2 * j + 1], hv0.y, a0);
            a1 = ffma2(w[2 * j],     hv1.x, a1);
            a1 = ffma2(w[2 * j + 1], hv1.y, a1);
        }
#pragma unroll
        for (int j = 0; j < 4; j++) {
            ulonglong2 wv  = wsm[j * 1024 + t];
            ulonglong2 hv0 = h0[12 + j];
            ulonglong2 hv1 = h1[12 + j];
            a0 = ffma2(wv.x, hv0.x, a0);
            a0 = ffma2(wv.y, hv0.y, a0);
            a1 = ffma2(wv.x, hv1.x, a1);
            a1 = ffma2(wv.y, hv1.y, a1);
        }

        float2 f;
        f = u2f(a0); float d0 = f.x + f.y;
        f = u2f(a1); float d1 = f.x + f.y;
        d0 += __shfl_xor_sync(0xffffffffu, d0, 1);
        d1 += __shfl_xor_sync(0xffffffffu, d1, 1);
        d0 += __shfl_xor_sync(0xffffffffu, d0, 2);
        d1 += __shfl_xor_sync(0xffffffffu, d1, 2);

        if (writer) {
            float hn = tanh_fast(((kq == 0) ? d0 : d1) + xv);
            hlast = hn;
            hbuf[(buf ^ 1) * H_BUF_F + wslot] = hn;
            if (myout) myout[(size_t)s * HID] = hn;
        }
        __syncthreads();
        buf ^= 1;
    }
    if (out_final && writer) out_final[(size_t)grow * HID + o] = hlast;
}

// ---------------------------------------------------------------------------
// GEMM v2 (unchanged from R2): Y[M,256] = X[M,K] @ W[256,K]^T + (ba+bb)
// Block tile 128M x 128N, 256 threads, thread tile 8x8, f32x2 accumulators.
// ---------------------------------------------------------------------------
template <int K>
__global__ __launch_bounds__(256, 2) void gemm2(
    const float* __restrict__ X, const float* __restrict__ W,
    const float* __restrict__ ba, const float* __restrict__ bb,
    float* __restrict__ Y)
{
    __shared__ float xs[16][128];
    __shared__ float ws[16][128];
    const int t  = threadIdx.x;
    const int tx = t & 15;
    const int ty = t >> 4;
    const size_t m0 = (size_t)blockIdx.x * 128;
    const int    n0 = blockIdx.y * 128;

    unsigned long long acc[8][4];
#pragma unroll
    for (int mi = 0; mi < 8; mi++)
#pragma unroll
        for (int ni = 0; ni < 4; ni++) acc[mi][ni] = 0ull;

    const int r = t & 127;
    const float* src_base = (t < 128) ? (X + (m0 + r) * K)
                                      : (W + (size_t)(n0 + r) * K);
    float* dst_col = (t < 128) ? &xs[0][r] : &ws[0][r];

    for (int kc = 0; kc < K; kc += 16) {
        const float4* src = reinterpret_cast<const float4*>(src_base + kc);
#pragma unroll
        for (int q = 0; q < 4; q++) {
            float4 v = src[q];
            dst_col[(4 * q + 0) * 128] = v.x;
            dst_col[(4 * q + 1) * 128] = v.y;
            dst_col[(4 * q + 2) * 128] = v.z;
            dst_col[(4 * q + 3) * 128] = v.w;
        }
        __syncthreads();

#pragma unroll
        for (int k = 0; k < 16; k++) {
            float4 a0 = *reinterpret_cast<const float4*>(&xs[k][ty * 8]);
            float4 a1 = *reinterpret_cast<const float4*>(&xs[k][ty * 8 + 4]);
            ulonglong2 b0 = *reinterpret_cast<const ulonglong2*>(&ws[k][tx * 8]);
            ulonglong2 b1 = *reinterpret_cast<const ulonglong2*>(&ws[k][tx * 8 + 4]);
            float am[8] = {a0.x, a0.y, a0.z, a0.w, a1.x, a1.y, a1.z, a1.w};
            unsigned long long bp0 = b0.x, bp1 = b0.y, bp2 = b1.x, bp3 = b1.y;
#pragma unroll
            for (int mi = 0; mi < 8; mi++) {
                unsigned long long am2 = pack2(am[mi], am[mi]);
                acc[mi][0] = ffma2(bp0, am2, acc[mi][0]);
                acc[mi][1] = ffma2(bp1, am2, acc[mi][1]);
                acc[mi][2] = ffma2(bp2, am2, acc[mi][2]);
                acc[mi][3] = ffma2(bp3, am2, acc[mi][3]);
            }
        }
        __syncthreads();
    }

    float bias[8];
#pragma unroll
    for (int i = 0; i < 8; i++)
        bias[i] = ba[n0 + tx * 8 + i] + bb[n0 + tx * 8 + i];

#pragma unroll
    for (int mi = 0; mi < 8; mi++) {
        float* yrow = Y + (m0 + ty * 8 + mi) * HID + n0 + tx * 8;
        float2 f0 = u2f(acc[mi][0]);
        float2 f1 = u2f(acc[mi][1]);
        float2 f2 = u2f(acc[mi][2]);
        float2 f3 = u2f(acc[mi][3]);
        float4 o0 = make_float4(f0.x + bias[0], f0.y + bias[1],
                                f1.x + bias[2], f1.y + bias[3]);
        float4 o1 = make_float4(f2.x + bias[4], f2.y + bias[5],
                                f3.x + bias[6], f3.y + bias[7]);
        reinterpret_cast<float4*>(yrow)[0] = o0;
        reinterpret_cast<float4*>(yrow)[1] = o1;
    }
}

// ---------------------------------------------------------------------------
// out[b] = sigmoid(h2[b,:] . Wfc + bfc)
// ---------------------------------------------------------------------------
__global__ void fc_sigmoid_kernel(const float* __restrict__ h2,
                                  const float* __restrict__ Wfc,
                                  const float* __restrict__ bfc,
                                  float* __restrict__ out)
{
    __shared__ float wf[HID];
    const int t = threadIdx.x;
    wf[t] = Wfc[t];
    __syncthreads();
    const float* hb = h2 + (size_t)t * HID;
    float s = 0.0f;
#pragma unroll 8
    for (int k = 0; k < HID; k++) s = fmaf(hb[k], wf[k], s);
    float z = s + bfc[0];
    out[t] = 1.0f / (1.0f + expf(-z));
}

// ---------------------------------------------------------------------------
// launch
// ---------------------------------------------------------------------------
extern "C" void kernel_launch(void* const* d_in, const int* in_sizes, int n_in,
                              void* d_out, int out_size)
{
    const float* x     = (const float*)d_in[0];
    const float* W_ih0 = (const float*)d_in[1];
    const float* W_hh0 = (const float*)d_in[2];
    const float* b_ih0 = (const float*)d_in[3];
    const float* b_hh0 = (const float*)d_in[4];
    const float* W_ih1 = (const float*)d_in[5];
    const float* W_hh1 = (const float*)d_in[6];
    const float* b_ih1 = (const float*)d_in[7];
    const float* b_hh1 = (const float*)d_in[8];
    const float* W_fc  = (const float*)d_in[9];
    const float* b_fc  = (const float*)d_in[10];
    float* out = (float*)d_out;

    float *bufA, *bufB, *hfin;
    cudaGetSymbolAddress((void**)&bufA, g_bufA);
    cudaGetSymbolAddress((void**)&bufB, g_bufB);
    cudaGetSymbolAddress((void**)&hfin, g_hfin);

    cudaFuncSetAttribute(rnn_recur3,
                         cudaFuncAttributeMaxDynamicSharedMemorySize,
                         RNN3_SMEM);

    const dim3 ggrid((BATCH * SEQ) / 128, 2);

    // A: xp0 = x @ W_ih0^T + (b_ih0 + b_hh0)
    gemm2<DIN><<<ggrid, 256>>>(x, W_ih0, b_ih0, b_hh0, bufA);
    // B: layer-0 recurrence -> h1 sequence
    rnn_recur3<<<BATCH / 2, 1024, RNN3_SMEM>>>(bufA, W_hh0, bufB, (float*)0);
    // C: xp1 = h1 @ W_ih1^T + (b_ih1 + b_hh1)
    gemm2<HID><<<ggrid, 256>>>(bufB, W_ih1, b_ih1, b_hh1, bufA);
    // D: layer-1 recurrence -> final hidden only
    rnn_recur3<<<BATCH / 2, 1024, RNN3_SMEM>>>(bufA, W_hh1, (float*)0, hfin);
    // E: fc + sigmoid
    fc_sigmoid_kernel<<<1, HID>>>(hfin, W_fc, b_fc, out);
}

// round 4
// speedup vs baseline: 1.8520x; 1.8520x over previous
#include <cuda_runtime.h>
#include <math.h>

#define BATCH 256
#define SEQ   512
#define DIN   64
#define HID   256

__device__ float g_bufA[(size_t)BATCH * SEQ * HID];   // 128 MiB
__device__ float g_bufB[(size_t)BATCH * SEQ * HID];   // 128 MiB
__device__ float g_hfin[(size_t)BATCH * HID];

// ---------------------------------------------------------------------------
// helpers
// ---------------------------------------------------------------------------
__device__ __forceinline__ unsigned long long ffma2(unsigned long long a,
                                                    unsigned long long b,
                                                    unsigned long long c) {
    unsigned long long d;
    asm("fma.rn.f32x2 %0, %1, %2, %3;" : "=l"(d) : "l"(a), "l"(b), "l"(c));
    return d;
}
__device__ __forceinline__ float2 u2f(unsigned long long v) {
    float2 r;
    asm("mov.b64 {%0, %1}, %2;" : "=f"(r.x), "=f"(r.y) : "l"(v));
    return r;
}
__device__ __forceinline__ unsigned long long pack2(float a, float b) {
    unsigned long long r;
    asm("mov.b64 %0, {%1, %2};" : "=l"(r) : "f"(a), "f"(b));
    return r;
}
__device__ __forceinline__ float tanh_fast(float x) {
    float r;
    asm("tanh.approx.f32 %0, %1;" : "=f"(r) : "f"(x));
    return r;
}

// ---------------------------------------------------------------------------
// Recurrence (proven R1 layout): 128 blocks x 512 threads, 2 rows/block.
// Thread t: o = t>>1, half = t&1. 96 weight floats in regs, 32 in smem.
// h double-buffered in smem (halves 132 floats apart -> bank-disjoint).
// Single shfl.xor(1) combines the two K-halves. tanh.approx epilogue.
// ---------------------------------------------------------------------------
__global__ __launch_bounds__(512, 1) void rnn_recur_kernel(
    const float* __restrict__ xp,      // [BATCH, SEQ, HID] (bias pre-added)
    const float* __restrict__ Whh,     // [HID, HID]
    float* __restrict__ out_seq,       // [BATCH, SEQ, HID] or null
    float* __restrict__ out_final)     // [BATCH, HID] or null
{
    __shared__ __align__(16) float hbuf[2][2][272];
    __shared__ ulonglong2 wsm[8][512];  // 64 KB: weight pairs 48..63 / thread

    const int t     = threadIdx.x;
    const int o     = t >> 1;
    const int half  = t & 1;
    const int myrow = blockIdx.x * 2 + half;

    const float* wrow = Whh + o * HID + half * 128;
    unsigned long long w[48];
#pragma unroll
    for (int q = 0; q < 24; q++) {
        ulonglong2 v = reinterpret_cast<const ulonglong2*>(wrow)[q];
        w[2 * q]     = v.x;
        w[2 * q + 1] = v.y;
    }
#pragma unroll
    for (int j = 0; j < 8; j++)
        wsm[j][t] = reinterpret_cast<const ulonglong2*>(wrow)[24 + j];

    for (int idx = t; idx < 2 * 272; idx += 512)
        (&hbuf[0][0][0])[idx] = 0.0f;
    __syncthreads();

    const float* myxp  = xp + (size_t)myrow * SEQ * HID + o;
    float*       myout = out_seq ? out_seq + (size_t)myrow * SEQ * HID + o
                                 : (float*)0;

    int   buf   = 0;
    float hlast = 0.0f;

    for (int s = 0; s < SEQ; s++) {
        float xv = __ldg(myxp + (size_t)s * HID);

        const ulonglong2* h0 =
            reinterpret_cast<const ulonglong2*>(&hbuf[buf][0][half * 132]);
        const ulonglong2* h1 =
            reinterpret_cast<const ulonglong2*>(&hbuf[buf][1][half * 132]);

        unsigned long long a0 = 0ull, a1 = 0ull;
#pragma unroll
        for (int q = 0; q < 24; q++) {          // register-resident weights
            ulonglong2 v0 = h0[q], v1 = h1[q];
            a0 = ffma2(w[2 * q],     v0.x, a0);
            a0 = ffma2(w[2 * q + 1], v0.y, a0);
            a1 = ffma2(w[2 * q],     v1.x, a1);
            a1 = ffma2(w[2 * q + 1], v1.y, a1);
        }
#pragma unroll
        for (int j = 0; j < 8; j++) {           // smem-resident weights
            ulonglong2 wv = wsm[j][t];
            ulonglong2 v0 = h0[24 + j], v1 = h1[24 + j];
            a0 = ffma2(wv.x, v0.x, a0);
            a0 = ffma2(wv.y, v0.y, a0);
            a1 = ffma2(wv.x, v1.x, a1);
            a1 = ffma2(wv.y, v1.y, a1);
        }

        float2 f0 = u2f(a0), f1 = u2f(a1);
        float  d0 = f0.x + f0.y;
        float  d1 = f1.x + f1.y;
        d0 += __shfl_xor_sync(0xffffffffu, d0, 1);
        d1 += __shfl_xor_sync(0xffffffffu, d1, 1);

        float hn = tanh_fast((half ? d1 : d0) + xv);
        hlast = hn;

        hbuf[buf ^ 1][half][o + 4 * (o >> 7)] = hn;
        if (out_seq) myout[(size_t)s * HID] = hn;

        __syncthreads();
        buf ^= 1;
    }

    if (out_final) out_final[(size_t)myrow * HID + o] = hlast;
}

// ---------------------------------------------------------------------------
// GEMM v3: Y[M,256] = X[M,K] @ W[256,K]^T + (ba+bb)
// Block tile 128M x 128N, 256 threads, thread tile 8x8 (f32x2 accumulators).
// Double-buffered smem staging: LDG of chunk i+1 overlaps compute of chunk i,
// single __syncthreads per chunk.
// ---------------------------------------------------------------------------
template <int K>
__global__ __launch_bounds__(256, 2) void gemm3(
    const float* __restrict__ X, const float* __restrict__ W,
    const float* __restrict__ ba, const float* __restrict__ bb,
    float* __restrict__ Y)
{
    __shared__ float xs[2][16][128];
    __shared__ float ws[2][16][128];
    const int t  = threadIdx.x;
    const int tx = t & 15;    // N: 16 x 8
    const int ty = t >> 4;    // M: 16 x 8
    const size_t m0 = (size_t)blockIdx.x * 128;
    const int    n0 = blockIdx.y * 128;

    unsigned long long acc[8][4];
#pragma unroll
    for (int mi = 0; mi < 8; mi++)
#pragma unroll
        for (int ni = 0; ni < 4; ni++) acc[mi][ni] = 0ull;

    const int r = t & 127;
    const float* src_base = (t < 128) ? (X + (m0 + r) * K)
                                      : (W + (size_t)(n0 + r) * K);

    // prologue: load + stage chunk 0
    float4 pf[4];
#pragma unroll
    for (int q = 0; q < 4; q++)
        pf[q] = reinterpret_cast<const float4*>(src_base)[q];

    int sb = 0;
    {
        float* dst = (t < 128) ? &xs[0][0][r] : &ws[0][0][r];
#pragma unroll
        for (int q = 0; q < 4; q++) {
            dst[(4 * q + 0) * 128] = pf[q].x;
            dst[(4 * q + 1) * 128] = pf[q].y;
            dst[(4 * q + 2) * 128] = pf[q].z;
            dst[(4 * q + 3) * 128] = pf[q].w;
        }
    }
    __syncthreads();

    for (int kc = 0; kc < K; kc += 16) {
        // issue LDG for next chunk before computing this one
        const bool have_next = (kc + 16 < K);
        if (have_next) {
            const float4* src =
                reinterpret_cast<const float4*>(src_base + kc + 16);
#pragma unroll
            for (int q = 0; q < 4; q++) pf[q] = src[q];
        }

#pragma unroll
        for (int k = 0; k < 16; k++) {
            float4 a0 = *reinterpret_cast<const float4*>(&xs[sb][k][ty * 8]);
            float4 a1 = *reinterpret_cast<const float4*>(&xs[sb][k][ty * 8 + 4]);
            ulonglong2 b0 =
                *reinterpret_cast<const ulonglong2*>(&ws[sb][k][tx * 8]);
            ulonglong2 b1 =
                *reinterpret_cast<const ulonglong2*>(&ws[sb][k][tx * 8 + 4]);
            float am[8] = {a0.x, a0.y, a0.z, a0.w, a1.x, a1.y, a1.z, a1.w};
            unsigned long long bp0 = b0.x, bp1 = b0.y, bp2 = b1.x, bp3 = b1.y;
#pragma unroll
            for (int mi = 0; mi < 8; mi++) {
                unsigned long long am2 = pack2(am[mi], am[mi]);
                acc[mi][0] = ffma2(bp0, am2, acc[mi][0]);
                acc[mi][1] = ffma2(bp1, am2, acc[mi][1]);
                acc[mi][2] = ffma2(bp2, am2, acc[mi][2]);
                acc[mi][3] = ffma2(bp3, am2, acc[mi][3]);
            }
        }

        if (have_next) {
            float* dst = (t < 128) ? &xs[sb ^ 1][0][r] : &ws[sb ^ 1][0][r];
#pragma unroll
            for (int q = 0; q < 4; q++) {
                dst[(4 * q + 0) * 128] = pf[q].x;
                dst[(4 * q + 1) * 128] = pf[q].y;
                dst[(4 * q + 2) * 128] = pf[q].z;
                dst[(4 * q + 3) * 128] = pf[q].w;
            }
            __syncthreads();
            sb ^= 1;
        }
    }

    float bias[8];
#pragma unroll
    for (int i = 0; i < 8; i++)
        bias[i] = ba[n0 + tx * 8 + i] + bb[n0 + tx * 8 + i];

#pragma unroll
    for (int mi = 0; mi < 8; mi++) {
        float* yrow = Y + (m0 + ty * 8 + mi) * HID + n0 + tx * 8;
        float2 f0 = u2f(acc[mi][0]);
        float2 f1 = u2f(acc[mi][1]);
        float2 f2 = u2f(acc[mi][2]);
        float2 f3 = u2f(acc[mi][3]);
        float4 o0 = make_float4(f0.x + bias[0], f0.y + bias[1],
                                f1.x + bias[2], f1.y + bias[3]);
        float4 o1 = make_float4(f2.x + bias[4], f2.y + bias[5],
                                f3.x + bias[6], f3.y + bias[7]);
        reinterpret_cast<float4*>(yrow)[0] = o0;
        reinterpret_cast<float4*>(yrow)[1] = o1;
    }
}

// ---------------------------------------------------------------------------
// out[b] = sigmoid(h2[b,:] . Wfc + bfc)
// ---------------------------------------------------------------------------
__global__ void fc_sigmoid_kernel(const float* __restrict__ h2,
                                  const float* __restrict__ Wfc,
                                  const float* __restrict__ bfc,
                                  float* __restrict__ out)
{
    __shared__ float wf[HID];
    const int t = threadIdx.x;
    wf[t] = Wfc[t];
    __syncthreads();
    const float* hb = h2 + (size_t)t * HID;
    float s = 0.0f;
#pragma unroll 8
    for (int k = 0; k < HID; k++) s = fmaf(hb[k], wf[k], s);
    float z = s + bfc[0];
    out[t] = 1.0f / (1.0f + expf(-z));
}

// ---------------------------------------------------------------------------
// launch
// ---------------------------------------------------------------------------
extern "C" void kernel_launch(void* const* d_in, const int* in_sizes, int n_in,
                              void* d_out, int out_size)
{
    const float* x     = (const float*)d_in[0];
    const float* W_ih0 = (const float*)d_in[1];
    const float* W_hh0 = (const float*)d_in[2];
    const float* b_ih0 = (const float*)d_in[3];
    const float* b_hh0 = (const float*)d_in[4];
    const float* W_ih1 = (const float*)d_in[5];
    const float* W_hh1 = (const float*)d_in[6];
    const float* b_ih1 = (const float*)d_in[7];
    const float* b_hh1 = (const float*)d_in[8];
    const float* W_fc  = (const float*)d_in[9];
    const float* b_fc  = (const float*)d_in[10];
    float* out = (float*)d_out;

    float *bufA, *bufB, *hfin;
    cudaGetSymbolAddress((void**)&bufA, g_bufA);
    cudaGetSymbolAddress((void**)&bufB, g_bufB);
    cudaGetSymbolAddress((void**)&hfin, g_hfin);

    const dim3 ggrid((BATCH * SEQ) / 128, 2);

    // A: xp0 = x @ W_ih0^T + (b_ih0 + b_hh0)
    gemm3<DIN><<<ggrid, 256>>>(x, W_ih0, b_ih0, b_hh0, bufA);
    // B: layer-0 recurrence -> h1 sequence
    rnn_recur_kernel<<<BATCH / 2, 512>>>(bufA, W_hh0, bufB, (float*)0);
    // C: xp1 = h1 @ W_ih1^T + (b_ih1 + b_hh1)
    gemm3<HID><<<ggrid, 256>>>(bufB, W_ih1, b_ih1, b_hh1, bufA);
    // D: layer-1 recurrence -> final hidden only
    rnn_recur_kernel<<<BATCH / 2, 512>>>(bufA, W_hh1, (float*)0, hfin);
    // E: fc + sigmoid
    fc_sigmoid_kernel<<<1, HID>>>(hfin, W_fc, b_fc, out);
}